// round 6
// baseline (speedup 1.0000x reference)
#include <cuda_runtime.h>
#include <cstdint>

#define N_TOK   98
#define N_DIM   512
#define N_HEADS 16
#define HD      32
#define N_BATCH 512
#define N_WIN   64
#define M_ROWS  (N_BATCH * N_TOK)   /* 50176 */
#define SCALE   0.17677669529663687f /* 32^-0.5 */

#define RS 36          /* q/k/v smem row stride */
#define SRS 100        /* score smem row stride */

#define G_RS2   20                  /* smem row stride in float2 units */
#define G_TILE2 (128 * G_RS2)       /* float2 per 128x16 tile = 2560 */

// ---- scratch (device globals: allocation-free rule) ----
__device__ float g_Q[(size_t)N_BATCH * N_HEADS * N_TOK * HD];
__device__ float g_K[(size_t)N_BATCH * N_HEADS * N_TOK * HD];
__device__ float g_V[(size_t)N_BATCH * N_HEADS * N_TOK * HD];
__device__ float g_Att[(size_t)M_ROWS * N_DIM];
__device__ float g_biasH[N_HEADS * N_TOK * N_TOK];

// ============================================================
// 1) Gather relative-position bias into per-head dense table
// ============================================================
__global__ void bias_pre_kernel(const float* __restrict__ bias_table,
                                const int* __restrict__ rel_index) {
    int idx = blockIdx.x * 256 + threadIdx.x;
    if (idx >= N_HEADS * N_TOK * N_TOK) return;
    int h  = idx / (N_TOK * N_TOK);
    int ij = idx % (N_TOK * N_TOK);
    g_biasH[idx] = bias_table[rel_index[ij] * N_HEADS + h];
}

// ============================================================
// helpers
// ============================================================
__device__ __forceinline__ uint32_t f2tf32(float f) {
    uint32_t r;
    asm("cvt.rna.tf32.f32 %0, %1;" : "=r"(r) : "f"(f));
    return r;
}
__device__ __forceinline__ void split_tf32(float f, uint32_t& hi, uint32_t& lo) {
    hi = f2tf32(f);
    float rem = f - __uint_as_float(hi);
    lo = f2tf32(rem);
}
// split a float4 and store as interleaved (hi,lo) float2 pairs: 2x STS.128
__device__ __forceinline__ void store_split4(float2* dst, float4 v) {
    uint32_t h0, l0, h1, l1, h2, l2, h3, l3;
    split_tf32(v.x, h0, l0);
    split_tf32(v.y, h1, l1);
    split_tf32(v.z, h2, l2);
    split_tf32(v.w, h3, l3);
    *(float4*)(dst)     = make_float4(__uint_as_float(h0), __uint_as_float(l0),
                                      __uint_as_float(h1), __uint_as_float(l1));
    *(float4*)(dst + 2) = make_float4(__uint_as_float(h2), __uint_as_float(l2),
                                      __uint_as_float(h3), __uint_as_float(l3));
}

#define MMA_TF32(c, a0, a1, a2, a3, b0, b1)                                  \
    asm volatile(                                                            \
        "mma.sync.aligned.m16n8k8.row.col.f32.tf32.tf32.f32 "                \
        "{%0,%1,%2,%3}, {%4,%5,%6,%7}, {%8,%9}, {%0,%1,%2,%3};"              \
        : "+f"(c[0]), "+f"(c[1]), "+f"(c[2]), "+f"(c[3])                     \
        : "r"(a0), "r"(a1), "r"(a2), "r"(a3), "r"(b0), "r"(b1))

// ============================================================
// 2) GEMM-NT on tensor cores, 3xTF32, 2-stage double buffer.
//    Split hi/lo ONCE at STS time; smem holds interleaved (hi,lo)
//    float2 -> fragment fetch = single LDS.64, zero mainloop ALU.
//    C[m,n] = sum_k A[m,k]*B[n,k]  (both K-major, K=512)
//    CTA tile 128x128x16, 8 warps (2x4), warp tile 64x32 (m16n8k8).
//    MODE 0: QKV epilogue (scatter to g_Q/g_K/g_V, scale q, +bias)
//    MODE 1: proj epilogue (A taken from g_Att, write Cout + bias)
// ============================================================
template <int MODE>
__global__ __launch_bounds__(256) void gemm_tc_kernel(
    const float* __restrict__ Ain, const float* __restrict__ B,
    const float* __restrict__ bias, float* __restrict__ Cout) {
    const int K = N_DIM;
    extern __shared__ float2 smem2[];
    float2* As = smem2;                 // [2][G_TILE2]
    float2* Bs = smem2 + 2 * G_TILE2;   // [2][G_TILE2]

    const float* A = (MODE == 1) ? g_Att : Ain;

    const int tid  = threadIdx.x;
    const int warp = tid >> 5, lane = tid & 31;
    const int wm = warp >> 2, wn = warp & 3;      // 2 x 4 warp grid
    const int m0 = blockIdx.y * 128;
    const int n0 = blockIdx.x * 128;

    // load coords: 512 float4 slots per tile, 2 per thread (A and B each)
    const int s0 = tid * 2,  s1 = tid * 2 + 1;
    const int r0 = s0 >> 2,  q0 = s0 & 3;
    const int r1 = s1 >> 2,  q1 = s1 & 3;
    const float* gA0 = A + (size_t)(m0 + r0) * K + q0 * 4;
    const float* gA1 = A + (size_t)(m0 + r1) * K + q1 * 4;
    const float* gB0 = B + (size_t)(n0 + r0) * K + q0 * 4;
    const float* gB1 = B + (size_t)(n0 + r1) * K + q1 * 4;
    const int dA0 = r0 * G_RS2 + q0 * 4;   // float2 index (even -> 16B aligned)
    const int dA1 = r1 * G_RS2 + q1 * 4;

    float c[4][4][4];
#pragma unroll
    for (int i = 0; i < 4; i++)
#pragma unroll
        for (int j = 0; j < 4; j++)
#pragma unroll
            for (int r = 0; r < 4; r++) c[i][j][r] = 0.f;

    // ---- prologue: chunk 0 into stage 0 ----
    store_split4(As + dA0, *(const float4*)gA0);
    store_split4(As + dA1, *(const float4*)gA1);
    store_split4(Bs + dA0, *(const float4*)gB0);
    store_split4(Bs + dA1, *(const float4*)gB1);
    __syncthreads();

    const int mroww = wm * 64 + (lane >> 2);
    const int ncoll = wn * 32 + (lane >> 2);
    const int kq    = lane & 3;
    const int NCHUNK = K / 16;   // 32

    float4 pa0, pa1, pb0, pb1;
    for (int kc = 0; kc < NCHUNK; kc++) {
        const int cur = kc & 1;
        const bool more = (kc + 1 < NCHUNK);
        if (more) {
            const int ko = (kc + 1) * 16;
            pa0 = *(const float4*)(gA0 + ko);
            pa1 = *(const float4*)(gA1 + ko);
            pb0 = *(const float4*)(gB0 + ko);
            pb1 = *(const float4*)(gB1 + ko);
        }

        const float2* Ast = As + cur * G_TILE2;
        const float2* Bst = Bs + cur * G_TILE2;
#pragma unroll
        for (int ks = 0; ks < 16; ks += 8) {
            uint32_t ah[4][4], al[4][4], bh[4][2], bl[4][2];
#pragma unroll
            for (int mt = 0; mt < 4; mt++) {
                const float2* p = Ast + (mroww + mt * 16) * G_RS2 + ks + kq;
                float2 v;
                v = p[0];              ah[mt][0] = __float_as_uint(v.x); al[mt][0] = __float_as_uint(v.y);
                v = p[8 * G_RS2];      ah[mt][1] = __float_as_uint(v.x); al[mt][1] = __float_as_uint(v.y);
                v = p[4];              ah[mt][2] = __float_as_uint(v.x); al[mt][2] = __float_as_uint(v.y);
                v = p[8 * G_RS2 + 4];  ah[mt][3] = __float_as_uint(v.x); al[mt][3] = __float_as_uint(v.y);
            }
#pragma unroll
            for (int nt = 0; nt < 4; nt++) {
                const float2* p = Bst + (ncoll + nt * 8) * G_RS2 + ks + kq;
                float2 v;
                v = p[0]; bh[nt][0] = __float_as_uint(v.x); bl[nt][0] = __float_as_uint(v.y);
                v = p[4]; bh[nt][1] = __float_as_uint(v.x); bl[nt][1] = __float_as_uint(v.y);
            }
#pragma unroll
            for (int mt = 0; mt < 4; mt++)
#pragma unroll
                for (int nt = 0; nt < 4; nt++) {
                    MMA_TF32(c[mt][nt], ah[mt][0], ah[mt][1], ah[mt][2], ah[mt][3],
                             bh[nt][0], bh[nt][1]);
                    MMA_TF32(c[mt][nt], ah[mt][0], ah[mt][1], ah[mt][2], ah[mt][3],
                             bl[nt][0], bl[nt][1]);
                    MMA_TF32(c[mt][nt], al[mt][0], al[mt][1], al[mt][2], al[mt][3],
                             bh[nt][0], bh[nt][1]);
                }
        }

        if (more) {
            float2* An = As + (cur ^ 1) * G_TILE2;
            float2* Bn = Bs + (cur ^ 1) * G_TILE2;
            store_split4(An + dA0, pa0);
            store_split4(An + dA1, pa1);
            store_split4(Bn + dA0, pb0);
            store_split4(Bn + dA1, pb1);
        }
        __syncthreads();
    }

    // ---- epilogue ----
#pragma unroll
    for (int nt = 0; nt < 4; nt++) {
        const int n = n0 + wn * 32 + nt * 8 + (lane & 3) * 2;
        const float b0v = bias[n], b1v = bias[n + 1];
        if (MODE == 1) {
#pragma unroll
            for (int mt = 0; mt < 4; mt++) {
                int m = m0 + wm * 64 + mt * 16 + (lane >> 2);
                *(float2*)(Cout + (size_t)m * N_DIM + n) =
                    make_float2(c[mt][nt][0] + b0v, c[mt][nt][1] + b1v);
                *(float2*)(Cout + (size_t)(m + 8) * N_DIM + n) =
                    make_float2(c[mt][nt][2] + b0v, c[mt][nt][3] + b1v);
            }
        } else {
            const int which = n >> 9;
            const int h = (n >> 5) & 15;
            const int d = n & 31;
            float* dst = (which == 0) ? g_Q : (which == 1 ? g_K : g_V);
            const float s = (which == 0) ? SCALE : 1.0f;
#pragma unroll
            for (int mt = 0; mt < 4; mt++) {
                int m = m0 + wm * 64 + mt * 16 + (lane >> 2);
                int b = m / N_TOK, tok = m - b * N_TOK;
                size_t off = (((size_t)b * N_HEADS + h) * N_TOK + tok) * HD + d;
                *(float2*)(dst + off) =
                    make_float2((c[mt][nt][0] + b0v) * s, (c[mt][nt][1] + b1v) * s);
                b = (m + 8) / N_TOK; tok = (m + 8) - b * N_TOK;
                off = (((size_t)b * N_HEADS + h) * N_TOK + tok) * HD + d;
                *(float2*)(dst + off) =
                    make_float2((c[mt][nt][2] + b0v) * s, (c[mt][nt][3] + b1v) * s);
            }
        }
    }
}

// ============================================================
// 3) Fused attention: one CTA per (b,h).
// ============================================================
__global__ __launch_bounds__(256, 2) void attn_kernel(const float* __restrict__ mask) {
    extern __shared__ float sm[];
    float* qsm = sm;              // 100 x RS
    float* ksm = sm + 100 * RS;
    float* vsm = sm + 200 * RS;
    float* Ssm = sm + 300 * RS;   // 100 x SRS

    const int tid = threadIdx.x;
    const int h = blockIdx.x;
    const int b = blockIdx.y;

    const size_t bh = (size_t)b * N_HEADS + h;
    const float* Qg = g_Q + bh * N_TOK * HD;
    const float* Kg = g_K + bh * N_TOK * HD;
    const float* Vg = g_V + bh * N_TOK * HD;

    for (int id = tid; id < 784; id += 256) {
        int row = id >> 3;
        int col = (id & 7) << 2;
        *(float4*)&qsm[row * RS + col] = *(const float4*)(Qg + id * 4);
        *(float4*)&ksm[row * RS + col] = *(const float4*)(Kg + id * 4);
        *(float4*)&vsm[row * RS + col] = *(const float4*)(Vg + id * 4);
    }
    if (tid < 72) {
        qsm[98 * RS + tid] = 0.f;
        ksm[98 * RS + tid] = 0.f;
        vsm[98 * RS + tid] = 0.f;
    }
    __syncthreads();

    const float* maskW = mask + (size_t)(b & (N_WIN - 1)) * N_TOK * N_TOK;
    const float* biasH = g_biasH + (size_t)h * N_TOK * N_TOK;
    for (int t = tid; t < 625; t += 256) {
        int ti = t / 25, tj = t % 25;
        float acc[4][4] = {};
#pragma unroll
        for (int d4 = 0; d4 < 8; d4++) {
            float4 qa[4], kb[4];
#pragma unroll
            for (int r = 0; r < 4; r++) qa[r] = *(float4*)&qsm[(ti * 4 + r) * RS + d4 * 4];
#pragma unroll
            for (int cc = 0; cc < 4; cc++) kb[cc] = *(float4*)&ksm[(tj * 4 + cc) * RS + d4 * 4];
#pragma unroll
            for (int r = 0; r < 4; r++)
#pragma unroll
                for (int cc = 0; cc < 4; cc++)
                    acc[r][cc] += qa[r].x * kb[cc].x + qa[r].y * kb[cc].y +
                                  qa[r].z * kb[cc].z + qa[r].w * kb[cc].w;
        }
#pragma unroll
        for (int r = 0; r < 4; r++) {
            int i = ti * 4 + r;
#pragma unroll
            for (int cc = 0; cc < 4; cc++) {
                int j = tj * 4 + cc;
                float v = acc[r][cc];
                if (i < N_TOK && j < N_TOK)
                    v += biasH[i * N_TOK + j] + maskW[i * N_TOK + j];
                Ssm[i * SRS + j] = v;
            }
        }
    }
    __syncthreads();

    const int warp = tid >> 5, lane = tid & 31;
    for (int i = warp; i < N_TOK; i += 8) {
        float* row = Ssm + i * SRS;
        float mx = -1e30f;
        for (int j = lane; j < N_TOK; j += 32) mx = fmaxf(mx, row[j]);
#pragma unroll
        for (int o = 16; o > 0; o >>= 1) mx = fmaxf(mx, __shfl_xor_sync(0xffffffffu, mx, o));
        float s = 0.f;
        for (int j = lane; j < N_TOK; j += 32) {
            float e = __expf(row[j] - mx);
            row[j] = e;
            s += e;
        }
#pragma unroll
        for (int o = 16; o > 0; o >>= 1) s += __shfl_xor_sync(0xffffffffu, s, o);
        float inv = 1.0f / s;
        for (int j = lane; j < N_TOK; j += 32) row[j] *= inv;
    }
    __syncthreads();

    if (tid < 200) {
        int ti = tid >> 3, dt = tid & 7;
        float acc[4][4] = {};
#pragma unroll 2
        for (int j = 0; j < N_TOK; j++) {
            float4 vv = *(float4*)&vsm[j * RS + dt * 4];
#pragma unroll
            for (int r = 0; r < 4; r++) {
                float p = Ssm[(ti * 4 + r) * SRS + j];
                acc[r][0] += p * vv.x;
                acc[r][1] += p * vv.y;
                acc[r][2] += p * vv.z;
                acc[r][3] += p * vv.w;
            }
        }
#pragma unroll
        for (int r = 0; r < 4; r++) {
            int i = ti * 4 + r;
            if (i < N_TOK) {
                float* dst = g_Att + ((size_t)(b * N_TOK + i)) * N_DIM + h * HD + dt * 4;
                *(float4*)dst = make_float4(acc[r][0], acc[r][1], acc[r][2], acc[r][3]);
            }
        }
    }
}

// ============================================================
extern "C" void kernel_launch(void* const* d_in, const int* in_sizes, int n_in,
                              void* d_out, int out_size) {
    const float* x          = (const float*)d_in[0];
    const float* mask       = (const float*)d_in[1];
    const float* qkv_w      = (const float*)d_in[2];
    const float* qkv_b      = (const float*)d_in[3];
    const float* proj_w     = (const float*)d_in[4];
    const float* proj_b     = (const float*)d_in[5];
    const float* bias_table = (const float*)d_in[6];
    const int*   rel_index  = (const int*)d_in[7];
    float* out = (float*)d_out;

    bias_pre_kernel<<<(N_HEADS * N_TOK * N_TOK + 255) / 256, 256>>>(bias_table, rel_index);

    const int gemm_smem = 4 * G_TILE2 * (int)sizeof(float2);   // 81920 B
    cudaFuncSetAttribute(gemm_tc_kernel<0>, cudaFuncAttributeMaxDynamicSharedMemorySize, gemm_smem);
    cudaFuncSetAttribute(gemm_tc_kernel<1>, cudaFuncAttributeMaxDynamicSharedMemorySize, gemm_smem);

    // QKV projection (M=50176, N=1536, K=512) -> scattered into g_Q/g_K/g_V
    gemm_tc_kernel<0><<<dim3(12, 392), 256, gemm_smem>>>(x, qkv_w, qkv_b, nullptr);

    // fused window attention
    const int attn_smem = (300 * RS + 100 * SRS) * (int)sizeof(float);  // 83200 B
    cudaFuncSetAttribute(attn_kernel, cudaFuncAttributeMaxDynamicSharedMemorySize, attn_smem);
    attn_kernel<<<dim3(N_HEADS, N_BATCH), 256, attn_smem>>>(mask);

    // output projection (M=50176, N=512, K=512) -> d_out
    gemm_tc_kernel<1><<<dim3(4, 392), 256, gemm_smem>>>(nullptr, proj_w, proj_b, out);
}

// round 9
// speedup vs baseline: 1.0827x; 1.0827x over previous
#include <cuda_runtime.h>
#include <cstdint>

#define N_TOK   98
#define N_DIM   512
#define N_HEADS 16
#define HD      32
#define N_BATCH 512
#define N_WIN   64
#define M_ROWS  (N_BATCH * N_TOK)   /* 50176 */
#define SCALE   0.17677669529663687f /* 32^-0.5 */

#define RS 36          /* q/k/v smem row stride */
#define SRS 100        /* score smem row stride */

#define AST 136        /* A smem k-row stride (128 M + 8 pad) */
#define BST 72         /* B smem k-row stride (64 N + 8 pad) */

// ---- scratch (device globals: allocation-free rule) ----
__device__ float g_Q[(size_t)N_BATCH * N_HEADS * N_TOK * HD];
__device__ float g_K[(size_t)N_BATCH * N_HEADS * N_TOK * HD];
__device__ float g_V[(size_t)N_BATCH * N_HEADS * N_TOK * HD];
__device__ float g_Att[(size_t)M_ROWS * N_DIM];
__device__ float g_biasH[N_HEADS * N_TOK * N_TOK];

// ============================================================
// 1) Gather relative-position bias into per-head dense table
// ============================================================
__global__ void bias_pre_kernel(const float* __restrict__ bias_table,
                                const int* __restrict__ rel_index) {
    int idx = blockIdx.x * 256 + threadIdx.x;
    if (idx >= N_HEADS * N_TOK * N_TOK) return;
    int h  = idx / (N_TOK * N_TOK);
    int ij = idx % (N_TOK * N_TOK);
    g_biasH[idx] = bias_table[rel_index[ij] * N_HEADS + h];
}

// ============================================================
// helpers
// ============================================================
__device__ __forceinline__ uint32_t f2tf32(float f) {
    uint32_t r;
    asm("cvt.rna.tf32.f32 %0, %1;" : "=r"(r) : "f"(f));
    return r;
}
__device__ __forceinline__ void split_tf32(float f, uint32_t& hi, uint32_t& lo) {
    hi = f2tf32(f);
    float rem = f - __uint_as_float(hi);
    lo = f2tf32(rem);
}

#define MMA_TF32(c, a0, a1, a2, a3, b0, b1)                                  \
    asm volatile(                                                            \
        "mma.sync.aligned.m16n8k8.row.col.f32.tf32.tf32.f32 "                \
        "{%0,%1,%2,%3}, {%4,%5,%6,%7}, {%8,%9}, {%0,%1,%2,%3};"              \
        : "+f"(c[0]), "+f"(c[1]), "+f"(c[2]), "+f"(c[3])                     \
        : "r"(a0), "r"(a1), "r"(a2), "r"(a3), "r"(b0), "r"(b1))

// ============================================================
// 2) GEMM-NT on tensor cores, 3xTF32. R2-proven structure
//    (split once at STS time) but CTA tile 128x64 / warp tile
//    32x32 so 2 CTAs co-reside per SM (occupancy 25%):
//    co-resident CTA covers the store/barrier phase gaps.
//    C[m,n] = sum_k A[m,k]*B[n,k]  (both K-major, K=512)
//    8 warps in 4(M) x 2(N) grid.
//    MODE 0: QKV epilogue (scatter to g_Q/g_K/g_V, scale q, +bias)
//    MODE 1: proj epilogue (A taken from g_Att, write Cout + bias)
// ============================================================
template <int MODE>
__global__ __launch_bounds__(256, 2) void gemm_tc_kernel(
    const float* __restrict__ Ain, const float* __restrict__ B,
    const float* __restrict__ bias, float* __restrict__ Cout) {
    const int K = N_DIM;
    __shared__ uint32_t Ah[16 * AST];
    __shared__ uint32_t Al[16 * AST];
    __shared__ uint32_t Bh[16 * BST];
    __shared__ uint32_t Bl[16 * BST];

    const float* A = (MODE == 1) ? g_Att : Ain;

    const int tid  = threadIdx.x;
    const int warp = tid >> 5, lane = tid & 31;
    const int wm = warp >> 1, wn = warp & 1;      // 4(M) x 2(N) warp grid
    const int m0 = blockIdx.y * 128;
    const int n0 = blockIdx.x * 64;

    // global load coords: A = 2 float4/thread (512 slots), B = 1 (256 slots)
    const int sa0 = tid * 2, sa1 = tid * 2 + 1;
    const int ra0 = sa0 >> 2, qa0 = (sa0 & 3) << 2;
    const int ra1 = sa1 >> 2, qa1 = (sa1 & 3) << 2;
    const int rb  = tid >> 2,  qb  = (tid & 3) << 2;
    const float* gA0 = A + (size_t)(m0 + ra0) * K + qa0;
    const float* gA1 = A + (size_t)(m0 + ra1) * K + qa1;
    const float* gB  = B + (size_t)(n0 + rb) * K + qb;

    float c[2][4][4];
#pragma unroll
    for (int i = 0; i < 2; i++)
#pragma unroll
        for (int j = 0; j < 4; j++)
#pragma unroll
            for (int r = 0; r < 4; r++) c[i][j][r] = 0.f;

    float4 pa0 = *(const float4*)gA0;
    float4 pa1 = *(const float4*)gA1;
    float4 pb  = *(const float4*)gB;

    const int mrow = wm * 32 + (lane >> 2);
    const int ncol = wn * 32 + (lane >> 2);
    const int kq   = lane & 3;

    for (int k0 = 0; k0 < K; k0 += 16) {
        // split + store prefetched chunk
        {
            uint32_t h, l;
            float v[4];
            v[0] = pa0.x; v[1] = pa0.y; v[2] = pa0.z; v[3] = pa0.w;
#pragma unroll
            for (int i = 0; i < 4; i++) {
                split_tf32(v[i], h, l);
                Ah[(qa0 + i) * AST + ra0] = h;
                Al[(qa0 + i) * AST + ra0] = l;
            }
            v[0] = pa1.x; v[1] = pa1.y; v[2] = pa1.z; v[3] = pa1.w;
#pragma unroll
            for (int i = 0; i < 4; i++) {
                split_tf32(v[i], h, l);
                Ah[(qa1 + i) * AST + ra1] = h;
                Al[(qa1 + i) * AST + ra1] = l;
            }
            v[0] = pb.x; v[1] = pb.y; v[2] = pb.z; v[3] = pb.w;
#pragma unroll
            for (int i = 0; i < 4; i++) {
                split_tf32(v[i], h, l);
                Bh[(qb + i) * BST + rb] = h;
                Bl[(qb + i) * BST + rb] = l;
            }
        }
        __syncthreads();

        // prefetch next chunk (LDG overlaps MMA below)
        if (k0 + 16 < K) {
            pa0 = *(const float4*)(gA0 + k0 + 16);
            pa1 = *(const float4*)(gA1 + k0 + 16);
            pb  = *(const float4*)(gB  + k0 + 16);
        }

#pragma unroll
        for (int ks = 0; ks < 16; ks += 8) {
            uint32_t ah[2][4], al[2][4], bh[4][2], bl[4][2];
            const int kb  = (ks + kq) * AST;
            const int kb4 = (ks + kq + 4) * AST;
#pragma unroll
            for (int mt = 0; mt < 2; mt++) {
                int m = mrow + mt * 16;
                ah[mt][0] = Ah[kb + m];      ah[mt][1] = Ah[kb + m + 8];
                ah[mt][2] = Ah[kb4 + m];     ah[mt][3] = Ah[kb4 + m + 8];
                al[mt][0] = Al[kb + m];      al[mt][1] = Al[kb + m + 8];
                al[mt][2] = Al[kb4 + m];     al[mt][3] = Al[kb4 + m + 8];
            }
            const int kc  = (ks + kq) * BST;
            const int kc4 = (ks + kq + 4) * BST;
#pragma unroll
            for (int nt = 0; nt < 4; nt++) {
                int n = ncol + nt * 8;
                bh[nt][0] = Bh[kc + n];      bh[nt][1] = Bh[kc4 + n];
                bl[nt][0] = Bl[kc + n];      bl[nt][1] = Bl[kc4 + n];
            }
#pragma unroll
            for (int mt = 0; mt < 2; mt++)
#pragma unroll
                for (int nt = 0; nt < 4; nt++) {
                    MMA_TF32(c[mt][nt], ah[mt][0], ah[mt][1], ah[mt][2], ah[mt][3],
                             bh[nt][0], bh[nt][1]);
                    MMA_TF32(c[mt][nt], ah[mt][0], ah[mt][1], ah[mt][2], ah[mt][3],
                             bl[nt][0], bl[nt][1]);
                    MMA_TF32(c[mt][nt], al[mt][0], al[mt][1], al[mt][2], al[mt][3],
                             bh[nt][0], bh[nt][1]);
                }
        }
        __syncthreads();
    }

    // ---- epilogue ----
#pragma unroll
    for (int nt = 0; nt < 4; nt++) {
        const int n = n0 + wn * 32 + nt * 8 + (lane & 3) * 2;
        const float b0v = bias[n], b1v = bias[n + 1];
        if (MODE == 1) {
#pragma unroll
            for (int mt = 0; mt < 2; mt++) {
                int m = m0 + wm * 32 + mt * 16 + (lane >> 2);
                *(float2*)(Cout + (size_t)m * N_DIM + n) =
                    make_float2(c[mt][nt][0] + b0v, c[mt][nt][1] + b1v);
                *(float2*)(Cout + (size_t)(m + 8) * N_DIM + n) =
                    make_float2(c[mt][nt][2] + b0v, c[mt][nt][3] + b1v);
            }
        } else {
            const int which = n >> 9;
            const int h = (n >> 5) & 15;
            const int d = n & 31;
            float* dst = (which == 0) ? g_Q : (which == 1 ? g_K : g_V);
            const float s = (which == 0) ? SCALE : 1.0f;
#pragma unroll
            for (int mt = 0; mt < 2; mt++) {
                int m = m0 + wm * 32 + mt * 16 + (lane >> 2);
                int b = m / N_TOK, tok = m - b * N_TOK;
                size_t off = (((size_t)b * N_HEADS + h) * N_TOK + tok) * HD + d;
                *(float2*)(dst + off) =
                    make_float2((c[mt][nt][0] + b0v) * s, (c[mt][nt][1] + b1v) * s);
                b = (m + 8) / N_TOK; tok = (m + 8) - b * N_TOK;
                off = (((size_t)b * N_HEADS + h) * N_TOK + tok) * HD + d;
                *(float2*)(dst + off) =
                    make_float2((c[mt][nt][2] + b0v) * s, (c[mt][nt][3] + b1v) * s);
            }
        }
    }
}

// ============================================================
// 3) Fused attention: one CTA per (b,h).
// ============================================================
__global__ __launch_bounds__(256, 2) void attn_kernel(const float* __restrict__ mask) {
    extern __shared__ float sm[];
    float* qsm = sm;              // 100 x RS
    float* ksm = sm + 100 * RS;
    float* vsm = sm + 200 * RS;
    float* Ssm = sm + 300 * RS;   // 100 x SRS

    const int tid = threadIdx.x;
    const int h = blockIdx.x;
    const int b = blockIdx.y;

    const size_t bh = (size_t)b * N_HEADS + h;
    const float* Qg = g_Q + bh * N_TOK * HD;
    const float* Kg = g_K + bh * N_TOK * HD;
    const float* Vg = g_V + bh * N_TOK * HD;

    for (int id = tid; id < 784; id += 256) {
        int row = id >> 3;
        int col = (id & 7) << 2;
        *(float4*)&qsm[row * RS + col] = *(const float4*)(Qg + id * 4);
        *(float4*)&ksm[row * RS + col] = *(const float4*)(Kg + id * 4);
        *(float4*)&vsm[row * RS + col] = *(const float4*)(Vg + id * 4);
    }
    if (tid < 72) {
        qsm[98 * RS + tid] = 0.f;
        ksm[98 * RS + tid] = 0.f;
        vsm[98 * RS + tid] = 0.f;
    }
    __syncthreads();

    const float* maskW = mask + (size_t)(b & (N_WIN - 1)) * N_TOK * N_TOK;
    const float* biasH = g_biasH + (size_t)h * N_TOK * N_TOK;
    for (int t = tid; t < 625; t += 256) {
        int ti = t / 25, tj = t % 25;
        float acc[4][4] = {};
#pragma unroll
        for (int d4 = 0; d4 < 8; d4++) {
            float4 qa[4], kb[4];
#pragma unroll
            for (int r = 0; r < 4; r++) qa[r] = *(float4*)&qsm[(ti * 4 + r) * RS + d4 * 4];
#pragma unroll
            for (int cc = 0; cc < 4; cc++) kb[cc] = *(float4*)&ksm[(tj * 4 + cc) * RS + d4 * 4];
#pragma unroll
            for (int r = 0; r < 4; r++)
#pragma unroll
                for (int cc = 0; cc < 4; cc++)
                    acc[r][cc] += qa[r].x * kb[cc].x + qa[r].y * kb[cc].y +
                                  qa[r].z * kb[cc].z + qa[r].w * kb[cc].w;
        }
#pragma unroll
        for (int r = 0; r < 4; r++) {
            int i = ti * 4 + r;
#pragma unroll
            for (int cc = 0; cc < 4; cc++) {
                int j = tj * 4 + cc;
                float v = acc[r][cc];
                if (i < N_TOK && j < N_TOK)
                    v += biasH[i * N_TOK + j] + maskW[i * N_TOK + j];
                Ssm[i * SRS + j] = v;
            }
        }
    }
    __syncthreads();

    const int warp = tid >> 5, lane = tid & 31;
    for (int i = warp; i < N_TOK; i += 8) {
        float* row = Ssm + i * SRS;
        float mx = -1e30f;
        for (int j = lane; j < N_TOK; j += 32) mx = fmaxf(mx, row[j]);
#pragma unroll
        for (int o = 16; o > 0; o >>= 1) mx = fmaxf(mx, __shfl_xor_sync(0xffffffffu, mx, o));
        float s = 0.f;
        for (int j = lane; j < N_TOK; j += 32) {
            float e = __expf(row[j] - mx);
            row[j] = e;
            s += e;
        }
#pragma unroll
        for (int o = 16; o > 0; o >>= 1) s += __shfl_xor_sync(0xffffffffu, s, o);
        float inv = 1.0f / s;
        for (int j = lane; j < N_TOK; j += 32) row[j] *= inv;
    }
    __syncthreads();

    if (tid < 200) {
        int ti = tid >> 3, dt = tid & 7;
        float acc[4][4] = {};
#pragma unroll 2
        for (int j = 0; j < N_TOK; j++) {
            float4 vv = *(float4*)&vsm[j * RS + dt * 4];
#pragma unroll
            for (int r = 0; r < 4; r++) {
                float p = Ssm[(ti * 4 + r) * SRS + j];
                acc[r][0] += p * vv.x;
                acc[r][1] += p * vv.y;
                acc[r][2] += p * vv.z;
                acc[r][3] += p * vv.w;
            }
        }
#pragma unroll
        for (int r = 0; r < 4; r++) {
            int i = ti * 4 + r;
            if (i < N_TOK) {
                float* dst = g_Att + ((size_t)(b * N_TOK + i)) * N_DIM + h * HD + dt * 4;
                *(float4*)dst = make_float4(acc[r][0], acc[r][1], acc[r][2], acc[r][3]);
            }
        }
    }
}

// ============================================================
extern "C" void kernel_launch(void* const* d_in, const int* in_sizes, int n_in,
                              void* d_out, int out_size) {
    const float* x          = (const float*)d_in[0];
    const float* mask       = (const float*)d_in[1];
    const float* qkv_w      = (const float*)d_in[2];
    const float* qkv_b      = (const float*)d_in[3];
    const float* proj_w     = (const float*)d_in[4];
    const float* proj_b     = (const float*)d_in[5];
    const float* bias_table = (const float*)d_in[6];
    const int*   rel_index  = (const int*)d_in[7];
    float* out = (float*)d_out;

    bias_pre_kernel<<<(N_HEADS * N_TOK * N_TOK + 255) / 256, 256>>>(bias_table, rel_index);

    // QKV projection (M=50176, N=1536, K=512) -> scattered into g_Q/g_K/g_V
    gemm_tc_kernel<0><<<dim3(24, 392), 256>>>(x, qkv_w, qkv_b, nullptr);

    // fused window attention
    const int attn_smem = (300 * RS + 100 * SRS) * (int)sizeof(float);  // 83200 B
    cudaFuncSetAttribute(attn_kernel, cudaFuncAttributeMaxDynamicSharedMemorySize, attn_smem);
    attn_kernel<<<dim3(N_HEADS, N_BATCH), 256, attn_smem>>>(mask);

    // output projection (M=50176, N=512, K=512) -> d_out
    gemm_tc_kernel<1><<<dim3(8, 392), 256>>>(nullptr, proj_w, proj_b, out);
}

// round 16
// speedup vs baseline: 1.4555x; 1.3443x over previous
#include <cuda_runtime.h>
#include <cstdint>

#define N_TOK   98
#define N_DIM   512
#define N_HEADS 16
#define HD      32
#define N_BATCH 512
#define N_WIN   64
#define M_ROWS  (N_BATCH * N_TOK)   /* 50176 */
#define SCALE   0.17677669529663687f /* 32^-0.5 */

#define RS 36          /* q/k/v smem row stride */
#define SRS 100        /* score smem row stride */

#define AST 136        /* smem k-pair row stride (128 + 8 pad), conflict-free */

// ---- scratch (device globals: allocation-free rule) ----
__device__ float g_Q[(size_t)N_BATCH * N_HEADS * N_TOK * HD];
__device__ float g_K[(size_t)N_BATCH * N_HEADS * N_TOK * HD];
__device__ float g_V[(size_t)N_BATCH * N_HEADS * N_TOK * HD];
__device__ float g_Att[(size_t)M_ROWS * N_DIM];
__device__ float g_biasH[N_HEADS * N_TOK * N_TOK];

// ============================================================
// 1) Gather relative-position bias into per-head dense table
// ============================================================
__global__ void bias_pre_kernel(const float* __restrict__ bias_table,
                                const int* __restrict__ rel_index) {
    int idx = blockIdx.x * 256 + threadIdx.x;
    if (idx >= N_HEADS * N_TOK * N_TOK) return;
    int h  = idx / (N_TOK * N_TOK);
    int ij = idx % (N_TOK * N_TOK);
    g_biasH[idx] = bias_table[rel_index[ij] * N_HEADS + h];
}

// ============================================================
// helpers: bf16 hi/lo split via pure bit ops (round-to-nearest-even)
// ============================================================
__device__ __forceinline__ uint32_t bf16_top(float f) {
    uint32_t u = __float_as_uint(f);
    return (u + 0x7FFFu + ((u >> 16) & 1u)) >> 16;   // RNE to bf16, return top 16 bits
}
// pairs (a,b) of consecutive k -> one packed hi word + one packed lo word
// packed layout: low half = element k, high half = element k+1 (bf16x2)
__device__ __forceinline__ void split_pack_bf16(float a, float b,
                                                uint32_t& hi, uint32_t& lo) {
    uint32_t ha = bf16_top(a);
    uint32_t hb = bf16_top(b);
    float ra = a - __uint_as_float(ha << 16);
    float rb = b - __uint_as_float(hb << 16);
    hi = ha | (hb << 16);
    lo = bf16_top(ra) | (bf16_top(rb) << 16);
}

#define MMA_BF16(c, a0, a1, a2, a3, b0, b1)                                  \
    asm volatile(                                                            \
        "mma.sync.aligned.m16n8k16.row.col.f32.bf16.bf16.f32 "               \
        "{%0,%1,%2,%3}, {%4,%5,%6,%7}, {%8,%9}, {%0,%1,%2,%3};"              \
        : "+f"(c[0]), "+f"(c[1]), "+f"(c[2]), "+f"(c[3])                     \
        : "r"(a0), "r"(a1), "r"(a2), "r"(a3), "r"(b0), "r"(b1))

// ============================================================
// 2) GEMM-NT on tensor cores, 3xBF16 (hi/lo split, drop lo*lo),
//    m16n8k16. R2-proven structure: split once at STS time.
//    C[m,n] = sum_k A[m,k]*B[n,k]  (both K-major, K=512)
//    CTA tile 128x128x16, 8 warps (2x4), warp tile 64x32.
//    Smem: packed bf16x2 (k,k+1) words -> fragment = 1 LDS.32,
//    half the tf32 traffic, half the MMA instructions.
//    MODE 0: QKV epilogue (scatter to g_Q/g_K/g_V, scale q, +bias)
//    MODE 1: proj epilogue (A taken from g_Att, write Cout + bias)
// ============================================================
template <int MODE>
__global__ __launch_bounds__(256) void gemm_tc_kernel(
    const float* __restrict__ Ain, const float* __restrict__ B,
    const float* __restrict__ bias, float* __restrict__ Cout) {
    const int K = N_DIM;
    // 8 k-pairs x 128(+8) packed words per array
    __shared__ uint32_t Ah[8 * AST];
    __shared__ uint32_t Al[8 * AST];
    __shared__ uint32_t Bh[8 * AST];
    __shared__ uint32_t Bl[8 * AST];

    const float* A = (MODE == 1) ? g_Att : Ain;

    const int tid  = threadIdx.x;
    const int warp = tid >> 5, lane = tid & 31;
    const int wm = warp >> 2, wn = warp & 3;      // 2(M) x 4(N) warp grid
    const int m0 = blockIdx.y * 128;
    const int n0 = blockIdx.x * 128;

    // global load coords: 512 float4 slots per operand, 2 per thread
    const int s0 = tid * 2,  s1 = tid * 2 + 1;
    const int r0 = s0 >> 2,  q0 = s0 & 3;         // q = k-quad (4 floats)
    const int r1 = s1 >> 2,  q1 = s1 & 3;
    const float* gA0 = A + (size_t)(m0 + r0) * K + q0 * 4;
    const float* gA1 = A + (size_t)(m0 + r1) * K + q1 * 4;
    const float* gB0 = B + (size_t)(n0 + r0) * K + q0 * 4;
    const float* gB1 = B + (size_t)(n0 + r1) * K + q1 * 4;
    const int p0 = q0 * 2;    // k-pair row base in smem
    const int p1 = q1 * 2;

    float c[4][4][4];
#pragma unroll
    for (int i = 0; i < 4; i++)
#pragma unroll
        for (int j = 0; j < 4; j++)
#pragma unroll
            for (int r = 0; r < 4; r++) c[i][j][r] = 0.f;

    float4 pa0 = *(const float4*)gA0;
    float4 pa1 = *(const float4*)gA1;
    float4 pb0 = *(const float4*)gB0;
    float4 pb1 = *(const float4*)gB1;

    const int mrow = wm * 64 + (lane >> 2);
    const int ncol = wn * 32 + (lane >> 2);
    const int kp   = lane & 3;                    // fragment k-pair index

    for (int k0 = 0; k0 < K; k0 += 16) {
        // ---- split + store prefetched chunk (packed bf16x2) ----
        {
            uint32_t h, l;
            split_pack_bf16(pa0.x, pa0.y, h, l);
            Ah[p0 * AST + r0] = h;  Al[p0 * AST + r0] = l;
            split_pack_bf16(pa0.z, pa0.w, h, l);
            Ah[(p0 + 1) * AST + r0] = h;  Al[(p0 + 1) * AST + r0] = l;
            split_pack_bf16(pa1.x, pa1.y, h, l);
            Ah[p1 * AST + r1] = h;  Al[p1 * AST + r1] = l;
            split_pack_bf16(pa1.z, pa1.w, h, l);
            Ah[(p1 + 1) * AST + r1] = h;  Al[(p1 + 1) * AST + r1] = l;
            split_pack_bf16(pb0.x, pb0.y, h, l);
            Bh[p0 * AST + r0] = h;  Bl[p0 * AST + r0] = l;
            split_pack_bf16(pb0.z, pb0.w, h, l);
            Bh[(p0 + 1) * AST + r0] = h;  Bl[(p0 + 1) * AST + r0] = l;
            split_pack_bf16(pb1.x, pb1.y, h, l);
            Bh[p1 * AST + r1] = h;  Bl[p1 * AST + r1] = l;
            split_pack_bf16(pb1.z, pb1.w, h, l);
            Bh[(p1 + 1) * AST + r1] = h;  Bl[(p1 + 1) * AST + r1] = l;
        }
        __syncthreads();

        // prefetch next chunk (LDG overlaps MMA below)
        if (k0 + 16 < K) {
            pa0 = *(const float4*)(gA0 + k0 + 16);
            pa1 = *(const float4*)(gA1 + k0 + 16);
            pb0 = *(const float4*)(gB0 + k0 + 16);
            pb1 = *(const float4*)(gB1 + k0 + 16);
        }

        // ---- one k16 step: load fragments, 3-term bf16 MMA ----
        {
            uint32_t ah[4][4], al[4][4], bh[4][2], bl[4][2];
            const int kb  = kp * AST;
            const int kb4 = (kp + 4) * AST;
#pragma unroll
            for (int mt = 0; mt < 4; mt++) {
                int m = mrow + mt * 16;
                ah[mt][0] = Ah[kb + m];      ah[mt][1] = Ah[kb + m + 8];
                ah[mt][2] = Ah[kb4 + m];     ah[mt][3] = Ah[kb4 + m + 8];
                al[mt][0] = Al[kb + m];      al[mt][1] = Al[kb + m + 8];
                al[mt][2] = Al[kb4 + m];     al[mt][3] = Al[kb4 + m + 8];
            }
#pragma unroll
            for (int nt = 0; nt < 4; nt++) {
                int n = ncol + nt * 8;
                bh[nt][0] = Bh[kb + n];      bh[nt][1] = Bh[kb4 + n];
                bl[nt][0] = Bl[kb + n];      bl[nt][1] = Bl[kb4 + n];
            }
#pragma unroll
            for (int mt = 0; mt < 4; mt++)
#pragma unroll
                for (int nt = 0; nt < 4; nt++) {
                    MMA_BF16(c[mt][nt], ah[mt][0], ah[mt][1], ah[mt][2], ah[mt][3],
                             bh[nt][0], bh[nt][1]);
                    MMA_BF16(c[mt][nt], ah[mt][0], ah[mt][1], ah[mt][2], ah[mt][3],
                             bl[nt][0], bl[nt][1]);
                    MMA_BF16(c[mt][nt], al[mt][0], al[mt][1], al[mt][2], al[mt][3],
                             bh[nt][0], bh[nt][1]);
                }
        }
        __syncthreads();
    }

    // ---- epilogue ----
#pragma unroll
    for (int nt = 0; nt < 4; nt++) {
        const int n = n0 + wn * 32 + nt * 8 + (lane & 3) * 2;
        const float b0v = bias[n], b1v = bias[n + 1];
        if (MODE == 1) {
#pragma unroll
            for (int mt = 0; mt < 4; mt++) {
                int m = m0 + wm * 64 + mt * 16 + (lane >> 2);
                *(float2*)(Cout + (size_t)m * N_DIM + n) =
                    make_float2(c[mt][nt][0] + b0v, c[mt][nt][1] + b1v);
                *(float2*)(Cout + (size_t)(m + 8) * N_DIM + n) =
                    make_float2(c[mt][nt][2] + b0v, c[mt][nt][3] + b1v);
            }
        } else {
            const int which = n >> 9;
            const int h = (n >> 5) & 15;
            const int d = n & 31;
            float* dst = (which == 0) ? g_Q : (which == 1 ? g_K : g_V);
            const float s = (which == 0) ? SCALE : 1.0f;
#pragma unroll
            for (int mt = 0; mt < 4; mt++) {
                int m = m0 + wm * 64 + mt * 16 + (lane >> 2);
                int b = m / N_TOK, tok = m - b * N_TOK;
                size_t off = (((size_t)b * N_HEADS + h) * N_TOK + tok) * HD + d;
                *(float2*)(dst + off) =
                    make_float2((c[mt][nt][0] + b0v) * s, (c[mt][nt][1] + b1v) * s);
                b = (m + 8) / N_TOK; tok = (m + 8) - b * N_TOK;
                off = (((size_t)b * N_HEADS + h) * N_TOK + tok) * HD + d;
                *(float2*)(dst + off) =
                    make_float2((c[mt][nt][2] + b0v) * s, (c[mt][nt][3] + b1v) * s);
            }
        }
    }
}

// ============================================================
// 3) Fused attention: one CTA per (b,h).
// ============================================================
__global__ __launch_bounds__(256, 2) void attn_kernel(const float* __restrict__ mask) {
    extern __shared__ float sm[];
    float* qsm = sm;              // 100 x RS
    float* ksm = sm + 100 * RS;
    float* vsm = sm + 200 * RS;
    float* Ssm = sm + 300 * RS;   // 100 x SRS

    const int tid = threadIdx.x;
    const int h = blockIdx.x;
    const int b = blockIdx.y;

    const size_t bh = (size_t)b * N_HEADS + h;
    const float* Qg = g_Q + bh * N_TOK * HD;
    const float* Kg = g_K + bh * N_TOK * HD;
    const float* Vg = g_V + bh * N_TOK * HD;

    for (int id = tid; id < 784; id += 256) {
        int row = id >> 3;
        int col = (id & 7) << 2;
        *(float4*)&qsm[row * RS + col] = *(const float4*)(Qg + id * 4);
        *(float4*)&ksm[row * RS + col] = *(const float4*)(Kg + id * 4);
        *(float4*)&vsm[row * RS + col] = *(const float4*)(Vg + id * 4);
    }
    if (tid < 72) {
        qsm[98 * RS + tid] = 0.f;
        ksm[98 * RS + tid] = 0.f;
        vsm[98 * RS + tid] = 0.f;
    }
    __syncthreads();

    const float* maskW = mask + (size_t)(b & (N_WIN - 1)) * N_TOK * N_TOK;
    const float* biasH = g_biasH + (size_t)h * N_TOK * N_TOK;
    for (int t = tid; t < 625; t += 256) {
        int ti = t / 25, tj = t % 25;
        float acc[4][4] = {};
#pragma unroll
        for (int d4 = 0; d4 < 8; d4++) {
            float4 qa[4], kb[4];
#pragma unroll
            for (int r = 0; r < 4; r++) qa[r] = *(float4*)&qsm[(ti * 4 + r) * RS + d4 * 4];
#pragma unroll
            for (int cc = 0; cc < 4; cc++) kb[cc] = *(float4*)&ksm[(tj * 4 + cc) * RS + d4 * 4];
#pragma unroll
            for (int r = 0; r < 4; r++)
#pragma unroll
                for (int cc = 0; cc < 4; cc++)
                    acc[r][cc] += qa[r].x * kb[cc].x + qa[r].y * kb[cc].y +
                                  qa[r].z * kb[cc].z + qa[r].w * kb[cc].w;
        }
#pragma unroll
        for (int r = 0; r < 4; r++) {
            int i = ti * 4 + r;
#pragma unroll
            for (int cc = 0; cc < 4; cc++) {
                int j = tj * 4 + cc;
                float v = acc[r][cc];
                if (i < N_TOK && j < N_TOK)
                    v += biasH[i * N_TOK + j] + maskW[i * N_TOK + j];
                Ssm[i * SRS + j] = v;
            }
        }
    }
    __syncthreads();

    const int warp = tid >> 5, lane = tid & 31;
    for (int i = warp; i < N_TOK; i += 8) {
        float* row = Ssm + i * SRS;
        float mx = -1e30f;
        for (int j = lane; j < N_TOK; j += 32) mx = fmaxf(mx, row[j]);
#pragma unroll
        for (int o = 16; o > 0; o >>= 1) mx = fmaxf(mx, __shfl_xor_sync(0xffffffffu, mx, o));
        float s = 0.f;
        for (int j = lane; j < N_TOK; j += 32) {
            float e = __expf(row[j] - mx);
            row[j] = e;
            s += e;
        }
#pragma unroll
        for (int o = 16; o > 0; o >>= 1) s += __shfl_xor_sync(0xffffffffu, s, o);
        float inv = 1.0f / s;
        for (int j = lane; j < N_TOK; j += 32) row[j] *= inv;
    }
    __syncthreads();

    if (tid < 200) {
        int ti = tid >> 3, dt = tid & 7;
        float acc[4][4] = {};
#pragma unroll 2
        for (int j = 0; j < N_TOK; j++) {
            float4 vv = *(float4*)&vsm[j * RS + dt * 4];
#pragma unroll
            for (int r = 0; r < 4; r++) {
                float p = Ssm[(ti * 4 + r) * SRS + j];
                acc[r][0] += p * vv.x;
                acc[r][1] += p * vv.y;
                acc[r][2] += p * vv.z;
                acc[r][3] += p * vv.w;
            }
        }
#pragma unroll
        for (int r = 0; r < 4; r++) {
            int i = ti * 4 + r;
            if (i < N_TOK) {
                float* dst = g_Att + ((size_t)(b * N_TOK + i)) * N_DIM + h * HD + dt * 4;
                *(float4*)dst = make_float4(acc[r][0], acc[r][1], acc[r][2], acc[r][3]);
            }
        }
    }
}

// ============================================================
extern "C" void kernel_launch(void* const* d_in, const int* in_sizes, int n_in,
                              void* d_out, int out_size) {
    const float* x          = (const float*)d_in[0];
    const float* mask       = (const float*)d_in[1];
    const float* qkv_w      = (const float*)d_in[2];
    const float* qkv_b      = (const float*)d_in[3];
    const float* proj_w     = (const float*)d_in[4];
    const float* proj_b     = (const float*)d_in[5];
    const float* bias_table = (const float*)d_in[6];
    const int*   rel_index  = (const int*)d_in[7];
    float* out = (float*)d_out;

    bias_pre_kernel<<<(N_HEADS * N_TOK * N_TOK + 255) / 256, 256>>>(bias_table, rel_index);

    // QKV projection (M=50176, N=1536, K=512) -> scattered into g_Q/g_K/g_V
    gemm_tc_kernel<0><<<dim3(12, 392), 256>>>(x, qkv_w, qkv_b, nullptr);

    // fused window attention
    const int attn_smem = (300 * RS + 100 * SRS) * (int)sizeof(float);  // 83200 B
    cudaFuncSetAttribute(attn_kernel, cudaFuncAttributeMaxDynamicSharedMemorySize, attn_smem);
    attn_kernel<<<dim3(N_HEADS, N_BATCH), 256, attn_smem>>>(mask);

    // output projection (M=50176, N=512, K=512) -> d_out
    gemm_tc_kernel<1><<<dim3(4, 392), 256>>>(nullptr, proj_w, proj_b, out);
}